// round 2
// baseline (speedup 1.0000x reference)
#include <cuda_runtime.h>
#include <cuda_bf16.h>
#include <cmath>
#include <cstdint>

// Problem constants
#define B_   2
#define L_   2048
#define DIM_ 1024
#define H_   16
#define DK_  64
#define M_   (B_ * L_)   // 4096
#define NEGV (-1e10f)

// Scratch (device globals: allocation-free rule)
__device__ float g_Q[B_ * H_ * L_ * DK_];   // [b*H+h][l][dk]
__device__ float g_K[B_ * H_ * L_ * DK_];
__device__ float g_V[B_ * H_ * L_ * DK_];
__device__ float g_MHA[M_ * DIM_];          // interleaved channels dk*16+h
__device__ int   g_mask_mode;               // 0=int32, 1=byte, 2=float32

// ---------------------------------------------------------------------------
// Mask dtype detection: int32 words are {0,1}; float32 words are {0,0x3F800000};
// packed bytes produce other word values (e.g. 0x00010000). Mutually exclusive.
// ---------------------------------------------------------------------------
__global__ void detect_mask_kernel(const unsigned int* __restrict__ w) {
    __shared__ int sawF, sawB;
    if (threadIdx.x == 0) { sawF = 0; sawB = 0; }
    __syncthreads();
    int f = 0, bb = 0;
    for (int i = threadIdx.x; i < 65536; i += 256) {
        unsigned v = w[i];
        if (v == 0x3F800000u) f = 1;
        else if (v > 1u)      bb = 1;
    }
    if (f)  atomicOr(&sawF, 1);
    if (bb) atomicOr(&sawB, 1);
    __syncthreads();
    if (threadIdx.x == 0)
        g_mask_mode = sawB ? 1 : (sawF ? 2 : 0);
}

// ---------------------------------------------------------------------------
// SGEMM: C[M,N] = A[M,K] * W[N,K]^T   (A, W row-major, K=1024 contiguous)
// 128x128 block, BK=8, 8x8 per thread, 256 threads.
// permute=0: plain row-major store.
// permute=1: store head-permuted: row m -> (b, l); col c -> (h=c&15, dk=c>>4);
//            dst = ((b*16+h)*2048 + l)*64 + dk
// ---------------------------------------------------------------------------
#define GBM 128
#define GBN 128
#define GBK 8

__global__ __launch_bounds__(256) void gemm_abt(
    const float* __restrict__ A, const float* __restrict__ W,
    float* __restrict__ C, int permute)
{
    __shared__ float As[GBK][GBM];
    __shared__ float Ws[GBK][GBN];

    const int tid = threadIdx.x;
    const int m0 = blockIdx.y * GBM;
    const int n0 = blockIdx.x * GBN;

    // loader mapping: 128 rows x 2 float4 per row
    const int lrow = tid >> 1;
    const int lcol = (tid & 1) * 4;

    // compute mapping: 8 warps in 4x2 grid; lane in 4x8
    const int w    = tid >> 5;
    const int lane = tid & 31;
    const int wr = w & 3;            // 0..3 -> 32 rows each
    const int wc = w >> 2;           // 0..1 -> 64 cols each
    const int lr = lane >> 3;        // 0..3
    const int lc = lane & 7;         // 0..7
    const int rowBase = wr * 32 + lr * 8;
    const int colBase = wc * 64 + lc * 8;

    float acc[8][8];
#pragma unroll
    for (int i = 0; i < 8; i++)
#pragma unroll
        for (int j = 0; j < 8; j++) acc[i][j] = 0.f;

    const float* Aptr = A + (size_t)(m0 + lrow) * DIM_ + lcol;
    const float* Wptr = W + (size_t)(n0 + lrow) * DIM_ + lcol;

    for (int k0 = 0; k0 < DIM_; k0 += GBK) {
        float4 a4 = *(const float4*)(Aptr + k0);
        float4 w4 = *(const float4*)(Wptr + k0);
        As[lcol + 0][lrow] = a4.x; As[lcol + 1][lrow] = a4.y;
        As[lcol + 2][lrow] = a4.z; As[lcol + 3][lrow] = a4.w;
        Ws[lcol + 0][lrow] = w4.x; Ws[lcol + 1][lrow] = w4.y;
        Ws[lcol + 2][lrow] = w4.z; Ws[lcol + 3][lrow] = w4.w;
        __syncthreads();

#pragma unroll
        for (int kk = 0; kk < GBK; kk++) {
            float ra[8], rb[8];
            *(float4*)&ra[0] = *(const float4*)&As[kk][rowBase];
            *(float4*)&ra[4] = *(const float4*)&As[kk][rowBase + 4];
            *(float4*)&rb[0] = *(const float4*)&Ws[kk][colBase];
            *(float4*)&rb[4] = *(const float4*)&Ws[kk][colBase + 4];
#pragma unroll
            for (int i = 0; i < 8; i++)
#pragma unroll
                for (int j = 0; j < 8; j++)
                    acc[i][j] = fmaf(ra[i], rb[j], acc[i][j]);
        }
        __syncthreads();
    }

    if (!permute) {
#pragma unroll
        for (int i = 0; i < 8; i++) {
            float* cp = C + (size_t)(m0 + rowBase + i) * DIM_ + n0 + colBase;
            *(float4*)cp       = *(float4*)&acc[i][0];
            *(float4*)(cp + 4) = *(float4*)&acc[i][4];
        }
    } else {
#pragma unroll
        for (int i = 0; i < 8; i++) {
            const int m  = m0 + rowBase + i;
            const int bb = m >> 11;            // / 2048
            const int qi = m & (L_ - 1);
#pragma unroll
            for (int j = 0; j < 8; j++) {
                const int c  = n0 + colBase + j;
                const int h  = c & 15;
                const int dk = c >> 4;
                g_Q[0]; // no-op to keep symbol (compiler ignores)
                C[(((size_t)bb * H_ + h) * L_ + qi) * DK_ + dk] = acc[i][j];
            }
        }
    }
}

// ---------------------------------------------------------------------------
// Flash attention: per (b,h) head, 128-query x 64-key tiles, dk=64, fp32.
// smem: Qs[128][64] | KT[64][64] (d-major) | Vs[64][64] | Ss[128][64] = 96KB
// 256 threads: ty=tid>>4 owns 8 rows, tx=tid&15 owns 4 cols.
// ---------------------------------------------------------------------------
#define FBM 128
#define FBN 64
#define SMEM_FLOATS (FBM*DK_ + DK_*FBN + FBN*DK_ + FBM*FBN)

__global__ __launch_bounds__(256) void flash_attn(
    const float* __restrict__ Q, const float* __restrict__ K,
    const float* __restrict__ V, const void* __restrict__ maskp,
    float* __restrict__ mha)
{
    extern __shared__ float sm[];
    float* Qs = sm;                    // [128][64]
    float* KT = Qs + FBM * DK_;        // [64][64], KT[d*64+o]
    float* Vs = KT + DK_ * FBN;        // [64][64], Vs[o*64+d]
    float* Ss = Vs + FBN * DK_;        // [128][64]

    const int tid = threadIdx.x;
    const int bh  = blockIdx.y;            // 0..31
    const int q0  = blockIdx.x * FBM;
    const int b   = bh >> 4;
    const int h   = bh & 15;
    const int ty  = tid >> 4;              // 0..15
    const int tx  = tid & 15;              // 0..15
    const int mode = g_mask_mode;

    const float* Qh = Q + (size_t)bh * L_ * DK_;
    const float* Kh = K + (size_t)bh * L_ * DK_;
    const float* Vh = V + (size_t)bh * L_ * DK_;

    // load Q tile: 8192 floats = 2048 float4
    {
        const float4* src = (const float4*)(Qh + (size_t)q0 * DK_);
        float4* dst = (float4*)Qs;
#pragma unroll
        for (int i = 0; i < 8; i++) dst[tid + i * 256] = src[tid + i * 256];
    }

    float m_r[8], l_r[8], acc[8][4];
#pragma unroll
    for (int i = 0; i < 8; i++) {
        m_r[i] = -INFINITY; l_r[i] = 0.f;
#pragma unroll
        for (int j = 0; j < 4; j++) acc[i][j] = 0.f;
    }

    for (int t = 0; t < L_ / FBN; t++) {
        __syncthreads();   // previous-iter smem consumers done

        // K tile -> KT transposed; V tile straight. 1024 float4 each.
        {
            const float4* ks = (const float4*)(Kh + (size_t)t * FBN * DK_);
#pragma unroll
            for (int i = 0; i < 4; i++) {
                int idx = tid + i * 256;
                int o   = idx >> 4;
                int d4  = (idx & 15) * 4;
                float4 vv = ks[idx];
                KT[(d4 + 0) * FBN + o] = vv.x;
                KT[(d4 + 1) * FBN + o] = vv.y;
                KT[(d4 + 2) * FBN + o] = vv.z;
                KT[(d4 + 3) * FBN + o] = vv.w;
            }
            const float4* vsrc = (const float4*)(Vh + (size_t)t * FBN * DK_);
            float4* vdst = (float4*)Vs;
#pragma unroll
            for (int i = 0; i < 4; i++) vdst[tid + i * 256] = vsrc[tid + i * 256];
        }
        __syncthreads();

        // scores S = Q K^T
        float s[8][4];
#pragma unroll
        for (int i = 0; i < 8; i++)
#pragma unroll
            for (int j = 0; j < 4; j++) s[i][j] = 0.f;

#pragma unroll 8
        for (int d = 0; d < DK_; d++) {
            float4 kb = *(const float4*)&KT[d * FBN + tx * 4];
#pragma unroll
            for (int i = 0; i < 8; i++) {
                float qv = Qs[(ty * 8 + i) * DK_ + d];
                s[i][0] = fmaf(qv, kb.x, s[i][0]);
                s[i][1] = fmaf(qv, kb.y, s[i][1]);
                s[i][2] = fmaf(qv, kb.z, s[i][2]);
                s[i][3] = fmaf(qv, kb.w, s[i][3]);
            }
        }

        // scale + mask
#pragma unroll
        for (int i = 0; i < 8; i++) {
            const int qi = q0 + ty * 8 + i;
            const size_t mb = ((size_t)b * L_ + qi) * L_ + (size_t)t * FBN + tx * 4;
#pragma unroll
            for (int j = 0; j < 4; j++) {
                float sv = s[i][j] * 0.125f;
                bool msk;
                if (mode == 1)      msk = ((const unsigned char*)maskp)[mb + j] != 0;
                else if (mode == 0) msk = ((const int*)maskp)[mb + j] != 0;
                else                msk = ((const float*)maskp)[mb + j] != 0.f;
                s[i][j] = msk ? NEGV : sv;
            }
        }

        // online softmax update
#pragma unroll
        for (int i = 0; i < 8; i++) {
            float mx = fmaxf(fmaxf(s[i][0], s[i][1]), fmaxf(s[i][2], s[i][3]));
#pragma unroll
            for (int off = 1; off < 16; off <<= 1)
                mx = fmaxf(mx, __shfl_xor_sync(0xffffffffu, mx, off));
            float mnew = fmaxf(m_r[i], mx);
            float corr = __expf(m_r[i] - mnew);
            m_r[i] = mnew;
            float lsum = 0.f;
#pragma unroll
            for (int j = 0; j < 4; j++) {
                float p = __expf(s[i][j] - mnew);
                s[i][j] = p;
                lsum += p;
            }
#pragma unroll
            for (int off = 1; off < 16; off <<= 1)
                lsum += __shfl_xor_sync(0xffffffffu, lsum, off);
            l_r[i] = l_r[i] * corr + lsum;
#pragma unroll
            for (int j = 0; j < 4; j++) acc[i][j] *= corr;
#pragma unroll
            for (int j = 0; j < 4; j++)
                Ss[(ty * 8 + i) * FBN + tx * 4 + j] = s[i][j];
        }
        __syncthreads();

        // PV: acc += P @ V
#pragma unroll 8
        for (int o = 0; o < FBN; o++) {
            float4 rv = *(const float4*)&Vs[o * DK_ + tx * 4];
#pragma unroll
            for (int i = 0; i < 8; i++) {
                float pv = Ss[(ty * 8 + i) * FBN + o];
                acc[i][0] = fmaf(pv, rv.x, acc[i][0]);
                acc[i][1] = fmaf(pv, rv.y, acc[i][1]);
                acc[i][2] = fmaf(pv, rv.z, acc[i][2]);
                acc[i][3] = fmaf(pv, rv.w, acc[i][3]);
            }
        }
    }

    // normalize + store interleaved (channel = d*16 + h)
#pragma unroll
    for (int i = 0; i < 8; i++) {
        const int qi = q0 + ty * 8 + i;
        const float inv = 1.0f / l_r[i];
        float* dst = mha + ((size_t)b * L_ + qi) * DIM_ + h;
#pragma unroll
        for (int j = 0; j < 4; j++) {
            const int d = tx * 4 + j;
            dst[d * H_] = acc[i][j] * inv;
        }
    }
}

// ---------------------------------------------------------------------------
extern "C" void kernel_launch(void* const* d_in, const int* in_sizes, int n_in,
                              void* d_out, int out_size)
{
    const float* q   = (const float*)d_in[0];
    const float* k   = (const float*)d_in[1];
    const float* v   = (const float*)d_in[2];
    const void*  msk = d_in[3];
    const float* Wq  = (const float*)d_in[4];
    const float* Wk  = (const float*)d_in[5];
    const float* Wv  = (const float*)d_in[6];
    const float* Wo  = (const float*)d_in[7];
    float* out = (float*)d_out;

    float *gq, *gk, *gv, *gm;
    cudaGetSymbolAddress((void**)&gq, g_Q);
    cudaGetSymbolAddress((void**)&gk, g_K);
    cudaGetSymbolAddress((void**)&gv, g_V);
    cudaGetSymbolAddress((void**)&gm, g_MHA);

    cudaFuncSetAttribute(flash_attn, cudaFuncAttributeMaxDynamicSharedMemorySize,
                         SMEM_FLOATS * (int)sizeof(float));

    detect_mask_kernel<<<1, 256>>>((const unsigned int*)msk);

    dim3 ggrid(DIM_ / GBN, M_ / GBM);   // (8, 32)
    gemm_abt<<<ggrid, 256>>>(q, Wq, gq, 1);
    gemm_abt<<<ggrid, 256>>>(k, Wk, gk, 1);
    gemm_abt<<<ggrid, 256>>>(v, Wv, gv, 1);

    flash_attn<<<dim3(L_ / FBM, B_ * H_), 256, SMEM_FLOATS * sizeof(float)>>>(
        gq, gk, gv, msk, gm);

    gemm_abt<<<ggrid, 256>>>(gm, Wo, out, 0);
}

// round 9
// speedup vs baseline: 1.1386x; 1.1386x over previous
#include <cuda_runtime.h>
#include <cstdint>
#include <cmath>

#define B_    2
#define L_    2048
#define DIM_  1024
#define H_    16
#define DK_   64
#define M_    (B_ * L_)
#define NEGV  (-1e10f)

__device__ float g_Q[B_ * H_ * L_ * DK_];
__device__ float g_K[B_ * H_ * L_ * DK_];
__device__ float g_V[B_ * H_ * L_ * DK_];
__device__ float g_MHA[M_ * DIM_];
__device__ int   g_mask_mode;

// ---------------------------------------------------------------------------
__global__ void detect_mask_kernel(const unsigned int* __restrict__ w) {
    __shared__ int sawF, sawB;
    if (threadIdx.x == 0) { sawF = 0; sawB = 0; }
    __syncthreads();
    int f = 0, bb = 0;
    for (int i = threadIdx.x; i < 65536; i += 256) {
        unsigned v = w[i];
        if (v == 0x3F800000u) f = 1;
        else if (v > 1u)      bb = 1;
    }
    if (f)  atomicOr(&sawF, 1);
    if (bb) atomicOr(&sawB, 1);
    __syncthreads();
    if (threadIdx.x == 0) g_mask_mode = sawB ? 1 : (sawF ? 2 : 0);
}

// ---------------------------------------------------------------------------
__device__ __forceinline__ uint32_t tf32_rna(float x) {
    uint32_t r;
    asm("cvt.rna.tf32.f32 %0, %1;" : "=r"(r) : "f"(x));
    return r;
}
__device__ __forceinline__ void tf32_split(float x, uint32_t& hi, uint32_t& lo) {
    hi = tf32_rna(x);
    lo = tf32_rna(x - __uint_as_float(hi));
}
__device__ __forceinline__ void mma_tf32(float* d, const uint32_t* a, const uint32_t* b) {
    asm("mma.sync.aligned.m16n8k8.row.col.f32.tf32.tf32.f32 "
        "{%0,%1,%2,%3}, {%4,%5,%6,%7}, {%8,%9}, {%0,%1,%2,%3};"
        : "+f"(d[0]), "+f"(d[1]), "+f"(d[2]), "+f"(d[3])
        : "r"(a[0]), "r"(a[1]), "r"(a[2]), "r"(a[3]), "r"(b[0]), "r"(b[1]));
}

// ---------------------------------------------------------------------------
// Split-tf32 GEMM via mma.sync: C[M,N] = A[M,K] * W[N,K]^T  (fp32-accurate).
// CTA 128x128, BK=32, 2-stage cp.async, 8 warps (4x2), warp tile 32x64.
// Smem pitch 36 floats -> conflict-free fragment loads (bank = 4*ty + tq).
// permute=1: store head-permuted [b*H+h][l][dk] (channel c -> h=c&15, dk=c>>4).
// ---------------------------------------------------------------------------
#define GP 36
#define GEMM_SMEM (2 * 2 * 128 * GP * 4)   // 73728 bytes

__global__ __launch_bounds__(256) void gemm_tc(
    const float* __restrict__ A, const float* __restrict__ W,
    float* __restrict__ C, int permute)
{
    extern __shared__ float sg[];
    const int tid  = threadIdx.x;
    const int lane = tid & 31, widx = tid >> 5;
    const int ty = lane >> 2, tq = lane & 3;
    const int wm = widx & 3, wn = widx >> 2;          // warp grid 4x2
    const int m0 = blockIdx.y * 128, n0 = blockIdx.x * 128;

    float acc[2][8][4];
#pragma unroll
    for (int mf = 0; mf < 2; mf++)
#pragma unroll
        for (int f = 0; f < 8; f++)
#pragma unroll
            for (int e = 0; e < 4; e++) acc[mf][f][e] = 0.f;

#define TILE_LOAD(t_, s_) do {                                                  \
        float* dA_ = sg + (s_) * (2 * 128 * GP);                                \
        float* dW_ = dA_ + 128 * GP;                                            \
        const int k0_ = (t_) * 32;                                              \
        _Pragma("unroll")                                                       \
        for (int i_ = 0; i_ < 4; i_++) {                                        \
            const int ci_  = tid + i_ * 256;                                    \
            const int row_ = ci_ >> 3;                                          \
            const int kc_  = (ci_ & 7) * 4;                                     \
            uint32_t da_ = (uint32_t)__cvta_generic_to_shared(dA_ + row_ * GP + kc_); \
            asm volatile("cp.async.cg.shared.global [%0], [%1], 16;"            \
                :: "r"(da_), "l"(A + (size_t)(m0 + row_) * DIM_ + k0_ + kc_));  \
            uint32_t dw_ = (uint32_t)__cvta_generic_to_shared(dW_ + row_ * GP + kc_); \
            asm volatile("cp.async.cg.shared.global [%0], [%1], 16;"            \
                :: "r"(dw_), "l"(W + (size_t)(n0 + row_) * DIM_ + k0_ + kc_));  \
        }                                                                       \
        asm volatile("cp.async.commit_group;" ::: "memory");                    \
    } while (0)

    TILE_LOAD(0, 0);

    for (int t = 0; t < DIM_ / 32; t++) {
        asm volatile("cp.async.wait_group 0;" ::: "memory");
        __syncthreads();
        if (t + 1 < DIM_ / 32) TILE_LOAD(t + 1, (t + 1) & 1);

        const float* sA = sg + (t & 1) * (2 * 128 * GP);
        const float* sW = sA + 128 * GP;

#pragma unroll
        for (int ks = 0; ks < 4; ks++) {
            const int c = ks * 8 + tq;
            uint32_t ah[2][4], al[2][4];
#pragma unroll
            for (int mf = 0; mf < 2; mf++) {
                const int r = wm * 32 + mf * 16 + ty;
                tf32_split(sA[r * GP + c],           ah[mf][0], al[mf][0]);
                tf32_split(sA[(r + 8) * GP + c],     ah[mf][1], al[mf][1]);
                tf32_split(sA[r * GP + c + 4],       ah[mf][2], al[mf][2]);
                tf32_split(sA[(r + 8) * GP + c + 4], ah[mf][3], al[mf][3]);
            }
#pragma unroll
            for (int f = 0; f < 8; f++) {
                const int nr = wn * 64 + f * 8 + ty;
                uint32_t bh[2], bl[2];
                tf32_split(sW[nr * GP + c],     bh[0], bl[0]);
                tf32_split(sW[nr * GP + c + 4], bh[1], bl[1]);
#pragma unroll
                for (int mf = 0; mf < 2; mf++) {
                    mma_tf32(acc[mf][f], ah[mf], bh);
                    mma_tf32(acc[mf][f], ah[mf], bl);
                    mma_tf32(acc[mf][f], al[mf], bh);
                }
            }
        }
    }
#undef TILE_LOAD

    if (!permute) {
#pragma unroll
        for (int mf = 0; mf < 2; mf++) {
            const int rg = m0 + wm * 32 + mf * 16 + ty;
#pragma unroll
            for (int f = 0; f < 8; f++) {
                const int cg = n0 + wn * 64 + f * 8 + 2 * tq;
                *(float2*)&C[(size_t)rg * DIM_ + cg] =
                    make_float2(acc[mf][f][0], acc[mf][f][1]);
                *(float2*)&C[(size_t)(rg + 8) * DIM_ + cg] =
                    make_float2(acc[mf][f][2], acc[mf][f][3]);
            }
        }
    } else {
#pragma unroll
        for (int mf = 0; mf < 2; mf++) {
            const int rbase = m0 + wm * 32 + mf * 16 + ty;
#pragma unroll
            for (int f = 0; f < 8; f++) {
#pragma unroll
                for (int e = 0; e < 4; e++) {
                    const int rg = rbase + (e >> 1) * 8;
                    const int bb = rg >> 11, ql = rg & (L_ - 1);
                    const int cg = n0 + wn * 64 + f * 8 + 2 * tq + (e & 1);
                    const int hh = cg & 15, dk = cg >> 4;
                    C[(((size_t)bb * H_ + hh) * L_ + ql) * DK_ + dk] = acc[mf][f][e];
                }
            }
        }
    }
}

// ---------------------------------------------------------------------------
// Flash attention (unchanged, proven): 128q x 64k tiles, dk=64, fp32 SIMT.
// ---------------------------------------------------------------------------
#define FBM 128
#define FBN 64
#define SMEM_FLOATS (FBM*DK_ + DK_*FBN + FBN*DK_ + FBM*FBN)

__global__ __launch_bounds__(256) void flash_attn(
    const float* __restrict__ Q, const float* __restrict__ K,
    const float* __restrict__ V, const void* __restrict__ maskp,
    float* __restrict__ mha)
{
    extern __shared__ float sm[];
    float* Qs = sm;
    float* KT = Qs + FBM * DK_;
    float* Vs = KT + DK_ * FBN;
    float* Ss = Vs + FBN * DK_;

    const int tid = threadIdx.x;
    const int bh  = blockIdx.y;
    const int q0  = blockIdx.x * FBM;
    const int b   = bh >> 4;
    const int h   = bh & 15;
    const int ty  = tid >> 4;
    const int tx  = tid & 15;
    const int mode = g_mask_mode;

    const float* Qh = Q + (size_t)bh * L_ * DK_;
    const float* Kh = K + (size_t)bh * L_ * DK_;
    const float* Vh = V + (size_t)bh * L_ * DK_;

    {
        const float4* src = (const float4*)(Qh + (size_t)q0 * DK_);
        float4* dst = (float4*)Qs;
#pragma unroll
        for (int i = 0; i < 8; i++) dst[tid + i * 256] = src[tid + i * 256];
    }

    float m_r[8], l_r[8], acc[8][4];
#pragma unroll
    for (int i = 0; i < 8; i++) {
        m_r[i] = -INFINITY; l_r[i] = 0.f;
#pragma unroll
        for (int j = 0; j < 4; j++) acc[i][j] = 0.f;
    }

    for (int t = 0; t < L_ / FBN; t++) {
        __syncthreads();
        {
            const float4* ks = (const float4*)(Kh + (size_t)t * FBN * DK_);
#pragma unroll
            for (int i = 0; i < 4; i++) {
                int idx = tid + i * 256;
                int o   = idx >> 4;
                int d4  = (idx & 15) * 4;
                float4 vv = ks[idx];
                KT[(d4 + 0) * FBN + o] = vv.x;
                KT[(d4 + 1) * FBN + o] = vv.y;
                KT[(d4 + 2) * FBN + o] = vv.z;
                KT[(d4 + 3) * FBN + o] = vv.w;
            }
            const float4* vsrc = (const float4*)(Vh + (size_t)t * FBN * DK_);
            float4* vdst = (float4*)Vs;
#pragma unroll
            for (int i = 0; i < 4; i++) vdst[tid + i * 256] = vsrc[tid + i * 256];
        }
        __syncthreads();

        float s[8][4];
#pragma unroll
        for (int i = 0; i < 8; i++)
#pragma unroll
            for (int j = 0; j < 4; j++) s[i][j] = 0.f;

#pragma unroll 8
        for (int d = 0; d < DK_; d++) {
            float4 kb = *(const float4*)&KT[d * FBN + tx * 4];
#pragma unroll
            for (int i = 0; i < 8; i++) {
                float qv = Qs[(ty * 8 + i) * DK_ + d];
                s[i][0] = fmaf(qv, kb.x, s[i][0]);
                s[i][1] = fmaf(qv, kb.y, s[i][1]);
                s[i][2] = fmaf(qv, kb.z, s[i][2]);
                s[i][3] = fmaf(qv, kb.w, s[i][3]);
            }
        }

#pragma unroll
        for (int i = 0; i < 8; i++) {
            const int qi = q0 + ty * 8 + i;
            const size_t mb = ((size_t)b * L_ + qi) * L_ + (size_t)t * FBN + tx * 4;
#pragma unroll
            for (int j = 0; j < 4; j++) {
                float sv = s[i][j] * 0.125f;
                bool msk;
                if (mode == 1)      msk = ((const unsigned char*)maskp)[mb + j] != 0;
                else if (mode == 0) msk = ((const int*)maskp)[mb + j] != 0;
                else                msk = ((const float*)maskp)[mb + j] != 0.f;
                s[i][j] = msk ? NEGV : sv;
            }
        }

#pragma unroll
        for (int i = 0; i < 8; i++) {
            float mx = fmaxf(fmaxf(s[i][0], s[i][1]), fmaxf(s[i][2], s[i][3]));
#pragma unroll
            for (int off = 1; off < 16; off <<= 1)
                mx = fmaxf(mx, __shfl_xor_sync(0xffffffffu, mx, off));
            float mnew = fmaxf(m_r[i], mx);
            float corr = __expf(m_r[i] - mnew);
            m_r[i] = mnew;
            float lsum = 0.f;
#pragma unroll
            for (int j = 0; j < 4; j++) {
                float p = __expf(s[i][j] - mnew);
                s[i][j] = p;
                lsum += p;
            }
#pragma unroll
            for (int off = 1; off < 16; off <<= 1)
                lsum += __shfl_xor_sync(0xffffffffu, lsum, off);
            l_r[i] = l_r[i] * corr + lsum;
#pragma unroll
            for (int j = 0; j < 4; j++) acc[i][j] *= corr;
#pragma unroll
            for (int j = 0; j < 4; j++)
                Ss[(ty * 8 + i) * FBN + tx * 4 + j] = s[i][j];
        }
        __syncthreads();

#pragma unroll 8
        for (int o = 0; o < FBN; o++) {
            float4 rv = *(const float4*)&Vs[o * DK_ + tx * 4];
#pragma unroll
            for (int i = 0; i < 8; i++) {
                float pv = Ss[(ty * 8 + i) * FBN + o];
                acc[i][0] = fmaf(pv, rv.x, acc[i][0]);
                acc[i][1] = fmaf(pv, rv.y, acc[i][1]);
                acc[i][2] = fmaf(pv, rv.z, acc[i][2]);
                acc[i][3] = fmaf(pv, rv.w, acc[i][3]);
            }
        }
    }

#pragma unroll
    for (int i = 0; i < 8; i++) {
        const int qi = q0 + ty * 8 + i;
        const float inv = 1.0f / l_r[i];
        float* dst = mha + ((size_t)b * L_ + qi) * DIM_ + h;
#pragma unroll
        for (int j = 0; j < 4; j++) {
            const int d = tx * 4 + j;
            dst[d * H_] = acc[i][j] * inv;
        }
    }
}

// ---------------------------------------------------------------------------
extern "C" void kernel_launch(void* const* d_in, const int* in_sizes, int n_in,
                              void* d_out, int out_size)
{
    const float* q   = (const float*)d_in[0];
    const float* k   = (const float*)d_in[1];
    const float* v   = (const float*)d_in[2];
    const void*  msk = d_in[3];
    const float* Wq  = (const float*)d_in[4];
    const float* Wk  = (const float*)d_in[5];
    const float* Wv  = (const float*)d_in[6];
    const float* Wo  = (const float*)d_in[7];
    float* out = (float*)d_out;

    float *gq, *gk, *gv, *gm;
    cudaGetSymbolAddress((void**)&gq, g_Q);
    cudaGetSymbolAddress((void**)&gk, g_K);
    cudaGetSymbolAddress((void**)&gv, g_V);
    cudaGetSymbolAddress((void**)&gm, g_MHA);

    cudaFuncSetAttribute(gemm_tc, cudaFuncAttributeMaxDynamicSharedMemorySize,
                         GEMM_SMEM);
    cudaFuncSetAttribute(flash_attn, cudaFuncAttributeMaxDynamicSharedMemorySize,
                         SMEM_FLOATS * (int)sizeof(float));

    detect_mask_kernel<<<1, 256>>>((const unsigned int*)msk);

    dim3 ggrid(DIM_ / 128, M_ / 128);   // (8, 32)
    gemm_tc<<<ggrid, 256, GEMM_SMEM>>>(q, Wq, gq, 1);
    gemm_tc<<<ggrid, 256, GEMM_SMEM>>>(k, Wk, gk, 1);
    gemm_tc<<<ggrid, 256, GEMM_SMEM>>>(v, Wv, gv, 1);

    flash_attn<<<dim3(L_ / FBM, B_ * H_), 256, SMEM_FLOATS * sizeof(float)>>>(
        gq, gk, gv, msk, gm);

    gemm_tc<<<ggrid, 256, GEMM_SMEM>>>(gm, Wo, out, 0);
}

// round 12
// speedup vs baseline: 1.2615x; 1.1079x over previous
#include <cuda_runtime.h>
#include <cstdint>
#include <cmath>

#define B_    2
#define L_    2048
#define DIM_  1024
#define H_    16
#define DK_   64
#define M_    (B_ * L_)
#define NEGV  (-1e10f)
#define LOG2E 1.4426950408889634f

__device__ float g_Q[B_ * H_ * L_ * DK_];
__device__ float g_K[B_ * H_ * L_ * DK_];
__device__ float g_V[B_ * H_ * L_ * DK_];
__device__ float g_MHA[M_ * DIM_];
__device__ int   g_mask_mode;

// ---------------------------------------------------------------------------
__global__ void detect_mask_kernel(const unsigned int* __restrict__ w) {
    __shared__ int sawF, sawB;
    if (threadIdx.x == 0) { sawF = 0; sawB = 0; }
    __syncthreads();
    int f = 0, bb = 0;
    for (int i = threadIdx.x; i < 65536; i += 256) {
        unsigned v = w[i];
        if (v == 0x3F800000u) f = 1;
        else if (v > 1u)      bb = 1;
    }
    if (f)  atomicOr(&sawF, 1);
    if (bb) atomicOr(&sawB, 1);
    __syncthreads();
    if (threadIdx.x == 0) g_mask_mode = sawB ? 1 : (sawF ? 2 : 0);
}

// ---------------------------------------------------------------------------
__device__ __forceinline__ uint32_t tf32_rna(float x) {
    uint32_t r;
    asm("cvt.rna.tf32.f32 %0, %1;" : "=r"(r) : "f"(x));
    return r;
}
__device__ __forceinline__ void tf32_split(float x, uint32_t& hi, uint32_t& lo) {
    hi = tf32_rna(x);
    lo = tf32_rna(x - __uint_as_float(hi));
}
__device__ __forceinline__ void mma_tf32(float* d, const uint32_t* a, const uint32_t* b) {
    asm("mma.sync.aligned.m16n8k8.row.col.f32.tf32.tf32.f32 "
        "{%0,%1,%2,%3}, {%4,%5,%6,%7}, {%8,%9}, {%0,%1,%2,%3};"
        : "+f"(d[0]), "+f"(d[1]), "+f"(d[2]), "+f"(d[3])
        : "r"(a[0]), "r"(a[1]), "r"(a[2]), "r"(a[3]), "r"(b[0]), "r"(b[1]));
}
// exp2 on the FFMA pipe (MUFU at rt=8 would bottleneck 134M exps).
__device__ __forceinline__ float fast_exp2(float y) {
    y = fmaxf(y, -125.0f);
    int j = __float2int_rn(y);
    float f = y - (float)j;
    float p = 1.535336188319500e-4f;
    p = fmaf(p, f, 1.339887440266574e-3f);
    p = fmaf(p, f, 9.618437357674640e-3f);
    p = fmaf(p, f, 5.550332471162809e-2f);
    p = fmaf(p, f, 2.402264791363012e-1f);
    p = fmaf(p, f, 6.931472028550421e-1f);
    p = fmaf(p, f, 1.0f);
    return p * __int_as_float((j + 127) << 23);
}

// ---------------------------------------------------------------------------
// Split-tf32 GEMM via mma.sync (unchanged from round 9 — validated).
// ---------------------------------------------------------------------------
#define GP 36
#define GEMM_SMEM (2 * 2 * 128 * GP * 4)

__global__ __launch_bounds__(256) void gemm_tc(
    const float* __restrict__ A, const float* __restrict__ W,
    float* __restrict__ C, int permute)
{
    extern __shared__ float sg[];
    const int tid  = threadIdx.x;
    const int lane = tid & 31, widx = tid >> 5;
    const int ty = lane >> 2, tq = lane & 3;
    const int wm = widx & 3, wn = widx >> 2;
    const int m0 = blockIdx.y * 128, n0 = blockIdx.x * 128;

    float acc[2][8][4];
#pragma unroll
    for (int mf = 0; mf < 2; mf++)
#pragma unroll
        for (int f = 0; f < 8; f++)
#pragma unroll
            for (int e = 0; e < 4; e++) acc[mf][f][e] = 0.f;

#define TILE_LOAD(t_, s_) do {                                                  \
        float* dA_ = sg + (s_) * (2 * 128 * GP);                                \
        float* dW_ = dA_ + 128 * GP;                                            \
        const int k0_ = (t_) * 32;                                              \
        _Pragma("unroll")                                                       \
        for (int i_ = 0; i_ < 4; i_++) {                                        \
            const int ci_  = tid + i_ * 256;                                    \
            const int row_ = ci_ >> 3;                                          \
            const int kc_  = (ci_ & 7) * 4;                                     \
            uint32_t da_ = (uint32_t)__cvta_generic_to_shared(dA_ + row_ * GP + kc_); \
            asm volatile("cp.async.cg.shared.global [%0], [%1], 16;"            \
                :: "r"(da_), "l"(A + (size_t)(m0 + row_) * DIM_ + k0_ + kc_));  \
            uint32_t dw_ = (uint32_t)__cvta_generic_to_shared(dW_ + row_ * GP + kc_); \
            asm volatile("cp.async.cg.shared.global [%0], [%1], 16;"            \
                :: "r"(dw_), "l"(W + (size_t)(n0 + row_) * DIM_ + k0_ + kc_));  \
        }                                                                       \
        asm volatile("cp.async.commit_group;" ::: "memory");                    \
    } while (0)

    TILE_LOAD(0, 0);

    for (int t = 0; t < DIM_ / 32; t++) {
        asm volatile("cp.async.wait_group 0;" ::: "memory");
        __syncthreads();
        if (t + 1 < DIM_ / 32) TILE_LOAD(t + 1, (t + 1) & 1);

        const float* sA = sg + (t & 1) * (2 * 128 * GP);
        const float* sW = sA + 128 * GP;

#pragma unroll
        for (int ks = 0; ks < 4; ks++) {
            const int c = ks * 8 + tq;
            uint32_t ah[2][4], al[2][4];
#pragma unroll
            for (int mf = 0; mf < 2; mf++) {
                const int r = wm * 32 + mf * 16 + ty;
                tf32_split(sA[r * GP + c],           ah[mf][0], al[mf][0]);
                tf32_split(sA[(r + 8) * GP + c],     ah[mf][1], al[mf][1]);
                tf32_split(sA[r * GP + c + 4],       ah[mf][2], al[mf][2]);
                tf32_split(sA[(r + 8) * GP + c + 4], ah[mf][3], al[mf][3]);
            }
#pragma unroll
            for (int f = 0; f < 8; f++) {
                const int nr = wn * 64 + f * 8 + ty;
                uint32_t bh[2], bl[2];
                tf32_split(sW[nr * GP + c],     bh[0], bl[0]);
                tf32_split(sW[nr * GP + c + 4], bh[1], bl[1]);
#pragma unroll
                for (int mf = 0; mf < 2; mf++) {
                    mma_tf32(acc[mf][f], ah[mf], bh);
                    mma_tf32(acc[mf][f], ah[mf], bl);
                    mma_tf32(acc[mf][f], al[mf], bh);
                }
            }
        }
    }
#undef TILE_LOAD

    if (!permute) {
#pragma unroll
        for (int mf = 0; mf < 2; mf++) {
            const int rg = m0 + wm * 32 + mf * 16 + ty;
#pragma unroll
            for (int f = 0; f < 8; f++) {
                const int cg = n0 + wn * 64 + f * 8 + 2 * tq;
                *(float2*)&C[(size_t)rg * DIM_ + cg] =
                    make_float2(acc[mf][f][0], acc[mf][f][1]);
                *(float2*)&C[(size_t)(rg + 8) * DIM_ + cg] =
                    make_float2(acc[mf][f][2], acc[mf][f][3]);
            }
        }
    } else {
#pragma unroll
        for (int mf = 0; mf < 2; mf++) {
            const int rbase = m0 + wm * 32 + mf * 16 + ty;
#pragma unroll
            for (int f = 0; f < 8; f++) {
#pragma unroll
                for (int e = 0; e < 4; e++) {
                    const int rg = rbase + (e >> 1) * 8;
                    const int bb = rg >> 11, ql = rg & (L_ - 1);
                    const int cg = n0 + wn * 64 + f * 8 + 2 * tq + (e & 1);
                    const int hh = cg & 15, dk = cg >> 4;
                    C[(((size_t)bb * H_ + hh) * L_ + ql) * DK_ + dk] = acc[mf][f][e];
                }
            }
        }
    }
}

// ---------------------------------------------------------------------------
// Split-tf32 mma.sync flash attention.
// Per (b,h): 128 queries/CTA (8 warps x 16 rows), 64 keys/iter, dk=64.
// QK^T and PV both 3-term split-tf32. Double-buffered cp.async K/V/mask.
// Smem pitch AP=68 -> conflict-free frag loads. P via per-warp smem region.
// ---------------------------------------------------------------------------
#define AP 68
#define STAGE_F (256 * AP)                       // K 64 + V 64 + mask 128 rows
#define ATTN_SMEM ((2 * STAGE_F + 128 * AP) * 4) // 174080 bytes

__global__ __launch_bounds__(256) void attn_tc(
    const float* __restrict__ Q, const float* __restrict__ K,
    const float* __restrict__ V, const void* __restrict__ maskp,
    float* __restrict__ mha)
{
    extern __shared__ float sa[];
    float* Ps = sa + 2 * STAGE_F;                // [128][AP] per-warp P staging

    const int tid  = threadIdx.x;
    const int lane = tid & 31, w = tid >> 5;
    const int ty = lane >> 2, tq = lane & 3;
    const int bh = blockIdx.y;
    const int b  = bh >> 4, h = bh & 15;
    const int q0 = blockIdx.x * 128;
    const int mode = g_mask_mode;

    const float* Qh = Q + (size_t)bh * L_ * DK_;
    const float* Kh = K + (size_t)bh * L_ * DK_;
    const float* Vh = V + (size_t)bh * L_ * DK_;

    // Q fragments (loop-invariant), split into hi/lo
    uint32_t qh[8][4], ql[8][4];
    {
        const float* qb = Qh + (size_t)(q0 + w * 16) * DK_;
#pragma unroll
        for (int ks = 0; ks < 8; ks++) {
            tf32_split(qb[ty * DK_ + ks * 8 + tq],           qh[ks][0], ql[ks][0]);
            tf32_split(qb[(ty + 8) * DK_ + ks * 8 + tq],     qh[ks][1], ql[ks][1]);
            tf32_split(qb[ty * DK_ + ks * 8 + tq + 4],       qh[ks][2], ql[ks][2]);
            tf32_split(qb[(ty + 8) * DK_ + ks * 8 + tq + 4], qh[ks][3], ql[ks][3]);
        }
    }

    float m_[2] = {-INFINITY, -INFINITY}, l_[2] = {0.f, 0.f};
    float acc[8][4];
#pragma unroll
    for (int nf = 0; nf < 8; nf++)
#pragma unroll
        for (int e = 0; e < 4; e++) acc[nf][e] = 0.f;

#define PREFETCH(t_, s_) do {                                                   \
        float* Kd_ = sa + (s_) * STAGE_F;                                       \
        float* Vd_ = Kd_ + 64 * AP;                                             \
        float* Md_ = Vd_ + 64 * AP;                                             \
        const float* Kg_ = Kh + (size_t)(t_) * 64 * DK_;                        \
        const float* Vg_ = Vh + (size_t)(t_) * 64 * DK_;                        \
        _Pragma("unroll")                                                       \
        for (int i_ = 0; i_ < 4; i_++) {                                        \
            int idx_ = tid + i_ * 256;                                          \
            int o_ = idx_ >> 4, c4_ = (idx_ & 15) * 4;                          \
            asm volatile("cp.async.cg.shared.global [%0], [%1], 16;"            \
                :: "r"((uint32_t)__cvta_generic_to_shared(Kd_ + o_ * AP + c4_)),\
                   "l"(Kg_ + o_ * DK_ + c4_) : "memory");                       \
            asm volatile("cp.async.cg.shared.global [%0], [%1], 16;"            \
                :: "r"((uint32_t)__cvta_generic_to_shared(Vd_ + o_ * AP + c4_)),\
                   "l"(Vg_ + o_ * DK_ + c4_) : "memory");                       \
        }                                                                       \
        if (mode != 1) {                                                        \
            const uint32_t* Mg_ = (const uint32_t*)maskp +                      \
                ((size_t)b * L_ + q0) * L_ + (size_t)(t_) * 64;                 \
            _Pragma("unroll")                                                   \
            for (int i_ = 0; i_ < 8; i_++) {                                    \
                int idx_ = tid + i_ * 256;                                      \
                int r_ = idx_ >> 4, c4_ = (idx_ & 15) * 4;                      \
                asm volatile("cp.async.cg.shared.global [%0], [%1], 16;"        \
                    :: "r"((uint32_t)__cvta_generic_to_shared(Md_ + r_ * AP + c4_)),\
                       "l"(Mg_ + (size_t)r_ * L_ + c4_) : "memory");            \
            }                                                                   \
        } else {                                                                \
            const unsigned char* Mg_ = (const unsigned char*)maskp +            \
                ((size_t)b * L_ + q0) * L_ + (size_t)(t_) * 64;                 \
            _Pragma("unroll")                                                   \
            for (int i_ = 0; i_ < 2; i_++) {                                    \
                int idx_ = tid + i_ * 256;                                      \
                int r_ = idx_ >> 2, c16_ = (idx_ & 3) * 16;                     \
                asm volatile("cp.async.cg.shared.global [%0], [%1], 16;"        \
                    :: "r"((uint32_t)__cvta_generic_to_shared((char*)Md_ + r_ * (AP * 4) + c16_)),\
                       "l"(Mg_ + (size_t)r_ * L_ + c16_) : "memory");           \
            }                                                                   \
        }                                                                       \
        asm volatile("cp.async.commit_group;" ::: "memory");                    \
    } while (0)

    PREFETCH(0, 0);

    const int rA = w * 16 + ty, rB = rA + 8;

    for (int t = 0; t < L_ / 64; t++) {
        if (t + 1 < L_ / 64) {
            PREFETCH(t + 1, (t + 1) & 1);
            asm volatile("cp.async.wait_group 1;" ::: "memory");
        } else {
            asm volatile("cp.async.wait_group 0;" ::: "memory");
        }
        __syncthreads();

        const float* Ksb = sa + (t & 1) * STAGE_F;
        const float* Vsb = Ksb + 64 * AP;
        const uint32_t* Mw = (const uint32_t*)(Vsb + 64 * AP);
        const unsigned char* Mb = (const unsigned char*)Mw;

        // S = Q K^T (3-term split-tf32)
        float s[8][4];
#pragma unroll
        for (int nf = 0; nf < 8; nf++)
#pragma unroll
            for (int e = 0; e < 4; e++) s[nf][e] = 0.f;

#pragma unroll
        for (int ks = 0; ks < 8; ks++) {
#pragma unroll
            for (int nf = 0; nf < 8; nf++) {
                uint32_t kh2[2], kl2[2];
                tf32_split(Ksb[(nf * 8 + ty) * AP + ks * 8 + tq],     kh2[0], kl2[0]);
                tf32_split(Ksb[(nf * 8 + ty) * AP + ks * 8 + tq + 4], kh2[1], kl2[1]);
                mma_tf32(s[nf], qh[ks], kh2);
                mma_tf32(s[nf], qh[ks], kl2);
                mma_tf32(s[nf], ql[ks], kh2);
            }
        }

        // scale + additive mask
#pragma unroll
        for (int nf = 0; nf < 8; nf++) {
            const int c0 = nf * 8 + 2 * tq;
#pragma unroll
            for (int e = 0; e < 2; e++) {
                bool mA, mB;
                if (mode == 1) {
                    mA = Mb[rA * (AP * 4) + c0 + e] != 0;
                    mB = Mb[rB * (AP * 4) + c0 + e] != 0;
                } else {
                    mA = Mw[rA * AP + c0 + e] != 0u;
                    mB = Mw[rB * AP + c0 + e] != 0u;
                }
                s[nf][e]     = s[nf][e]     * 0.125f + (mA ? NEGV : 0.f);
                s[nf][e + 2] = s[nf][e + 2] * 0.125f + (mB ? NEGV : 0.f);
            }
        }

        // online softmax (rows rA via e0/e1, rB via e2/e3; quad = lanes tq)
        float mxA = -INFINITY, mxB = -INFINITY;
#pragma unroll
        for (int nf = 0; nf < 8; nf++) {
            mxA = fmaxf(mxA, fmaxf(s[nf][0], s[nf][1]));
            mxB = fmaxf(mxB, fmaxf(s[nf][2], s[nf][3]));
        }
        mxA = fmaxf(mxA, __shfl_xor_sync(0xffffffffu, mxA, 1));
        mxA = fmaxf(mxA, __shfl_xor_sync(0xffffffffu, mxA, 2));
        mxB = fmaxf(mxB, __shfl_xor_sync(0xffffffffu, mxB, 1));
        mxB = fmaxf(mxB, __shfl_xor_sync(0xffffffffu, mxB, 2));

        const float mnA = fmaxf(m_[0], mxA), mnB = fmaxf(m_[1], mxB);
        const float corrA = fast_exp2((m_[0] - mnA) * LOG2E);
        const float corrB = fast_exp2((m_[1] - mnB) * LOG2E);
        m_[0] = mnA; m_[1] = mnB;

        float sumA = 0.f, sumB = 0.f;
#pragma unroll
        for (int nf = 0; nf < 8; nf++) {
            float p0 = fast_exp2((s[nf][0] - mnA) * LOG2E);
            float p1 = fast_exp2((s[nf][1] - mnA) * LOG2E);
            float p2 = fast_exp2((s[nf][2] - mnB) * LOG2E);
            float p3 = fast_exp2((s[nf][3] - mnB) * LOG2E);
            sumA += p0 + p1; sumB += p2 + p3;
            *(float2*)&Ps[rA * AP + nf * 8 + 2 * tq] = make_float2(p0, p1);
            *(float2*)&Ps[rB * AP + nf * 8 + 2 * tq] = make_float2(p2, p3);
        }
        sumA += __shfl_xor_sync(0xffffffffu, sumA, 1);
        sumA += __shfl_xor_sync(0xffffffffu, sumA, 2);
        sumB += __shfl_xor_sync(0xffffffffu, sumB, 1);
        sumB += __shfl_xor_sync(0xffffffffu, sumB, 2);
        l_[0] = l_[0] * corrA + sumA;
        l_[1] = l_[1] * corrB + sumB;
#pragma unroll
        for (int nf = 0; nf < 8; nf++) {
            acc[nf][0] *= corrA; acc[nf][1] *= corrA;
            acc[nf][2] *= corrB; acc[nf][3] *= corrB;
        }
        __syncwarp();

        // O += P V (3-term split-tf32); V natural [o][dk]: B[n=dk][k=o]
#pragma unroll
        for (int ks = 0; ks < 8; ks++) {
            uint32_t ah2[4], al2[4];
            tf32_split(Ps[rA * AP + ks * 8 + tq],     ah2[0], al2[0]);
            tf32_split(Ps[rB * AP + ks * 8 + tq],     ah2[1], al2[1]);
            tf32_split(Ps[rA * AP + ks * 8 + tq + 4], ah2[2], al2[2]);
            tf32_split(Ps[rB * AP + ks * 8 + tq + 4], ah2[3], al2[3]);
#pragma unroll
            for (int nf = 0; nf < 8; nf++) {
                uint32_t vh2[2], vl2[2];
                tf32_split(Vsb[(ks * 8 + tq) * AP + nf * 8 + ty],     vh2[0], vl2[0]);
                tf32_split(Vsb[(ks * 8 + tq + 4) * AP + nf * 8 + ty], vh2[1], vl2[1]);
                mma_tf32(acc[nf], ah2, vh2);
                mma_tf32(acc[nf], ah2, vl2);
                mma_tf32(acc[nf], al2, vh2);
            }
        }
        __syncthreads();   // all warps done with stage t&1 before it is refilled
    }
#undef PREFETCH

    // normalize + interleaved store (channel = dk*16 + h)
    const float invA = 1.f / l_[0], invB = 1.f / l_[1];
    const int qA = q0 + w * 16 + ty, qB = qA + 8;
    float* dA = mha + ((size_t)b * L_ + qA) * DIM_ + h;
    float* dB = mha + ((size_t)b * L_ + qB) * DIM_ + h;
#pragma unroll
    for (int nf = 0; nf < 8; nf++) {
        const int c0 = nf * 8 + 2 * tq;
        dA[c0 * 16]       = acc[nf][0] * invA;
        dA[(c0 + 1) * 16] = acc[nf][1] * invA;
        dB[c0 * 16]       = acc[nf][2] * invB;
        dB[(c0 + 1) * 16] = acc[nf][3] * invB;
    }
}

// ---------------------------------------------------------------------------
extern "C" void kernel_launch(void* const* d_in, const int* in_sizes, int n_in,
                              void* d_out, int out_size)
{
    const float* q   = (const float*)d_in[0];
    const float* k   = (const float*)d_in[1];
    const float* v   = (const float*)d_in[2];
    const void*  msk = d_in[3];
    const float* Wq  = (const float*)d_in[4];
    const float* Wk  = (const float*)d_in[5];
    const float* Wv  = (const float*)d_in[6];
    const float* Wo  = (const float*)d_in[7];
    float* out = (float*)d_out;

    float *gq, *gk, *gv, *gm;
    cudaGetSymbolAddress((void**)&gq, g_Q);
    cudaGetSymbolAddress((void**)&gk, g_K);
    cudaGetSymbolAddress((void**)&gv, g_V);
    cudaGetSymbolAddress((void**)&gm, g_MHA);

    cudaFuncSetAttribute(gemm_tc, cudaFuncAttributeMaxDynamicSharedMemorySize,
                         GEMM_SMEM);
    cudaFuncSetAttribute(attn_tc, cudaFuncAttributeMaxDynamicSharedMemorySize,
                         ATTN_SMEM);

    detect_mask_kernel<<<1, 256>>>((const unsigned int*)msk);

    dim3 ggrid(DIM_ / 128, M_ / 128);   // (8, 32)
    gemm_tc<<<ggrid, 256, GEMM_SMEM>>>(q, Wq, gq, 1);
    gemm_tc<<<ggrid, 256, GEMM_SMEM>>>(k, Wk, gk, 1);
    gemm_tc<<<ggrid, 256, GEMM_SMEM>>>(v, Wv, gv, 1);

    attn_tc<<<dim3(L_ / 128, B_ * H_), 256, ATTN_SMEM>>>(gq, gk, gv, msk, gm);

    gemm_tc<<<ggrid, 256, GEMM_SMEM>>>(gm, Wo, out, 0);
}

// round 15
// speedup vs baseline: 2.4109x; 1.9111x over previous
#include <cuda_runtime.h>
#include <cstdint>
#include <cmath>

#define B_    2
#define L_    2048
#define DIM_  1024
#define H_    16
#define DK_   64
#define M_    (B_ * L_)
#define NEGV  (-1e10f)
#define LOG2E 1.4426950408889634f

__device__ float g_Q[B_ * H_ * L_ * DK_];
__device__ float g_K[B_ * H_ * L_ * DK_];
__device__ float g_V[B_ * H_ * L_ * DK_];
__device__ float g_MHA[M_ * DIM_];
__device__ int   g_mask_mode;

// ---------------------------------------------------------------------------
__global__ void detect_mask_kernel(const unsigned int* __restrict__ w) {
    __shared__ int sawF, sawB;
    if (threadIdx.x == 0) { sawF = 0; sawB = 0; }
    __syncthreads();
    int f = 0, bb = 0;
    for (int i = threadIdx.x; i < 65536; i += 256) {
        unsigned v = w[i];
        if (v == 0x3F800000u) f = 1;
        else if (v > 1u)      bb = 1;
    }
    if (f)  atomicOr(&sawF, 1);
    if (bb) atomicOr(&sawB, 1);
    __syncthreads();
    if (threadIdx.x == 0) g_mask_mode = sawB ? 1 : (sawF ? 2 : 0);
}

// ---------------------------------------------------------------------------
// bf16 split: x = hi + lo, both bf16; packs pairs (x0 low half, x1 high half).
__device__ __forceinline__ void bf16_split2(float x0, float x1,
                                            uint32_t& hi, uint32_t& lo) {
    asm("cvt.rn.bf16x2.f32 %0, %1, %2;" : "=r"(hi) : "f"(x1), "f"(x0));
    float h0 = __uint_as_float(hi << 16);
    float h1 = __uint_as_float(hi & 0xffff0000u);
    asm("cvt.rn.bf16x2.f32 %0, %1, %2;" : "=r"(lo) : "f"(x1 - h1), "f"(x0 - h0));
}
__device__ __forceinline__ void mma_bf16(float* d, const uint32_t* a, const uint32_t* b) {
    asm("mma.sync.aligned.m16n8k16.row.col.f32.bf16.bf16.f32 "
        "{%0,%1,%2,%3}, {%4,%5,%6,%7}, {%8,%9}, {%0,%1,%2,%3};"
        : "+f"(d[0]), "+f"(d[1]), "+f"(d[2]), "+f"(d[3])
        : "r"(a[0]), "r"(a[1]), "r"(a[2]), "r"(a[3]), "r"(b[0]), "r"(b[1]));
}
__device__ __forceinline__ void ldm_x4(uint32_t* r, uint32_t addr) {
    asm volatile("ldmatrix.sync.aligned.m8n8.x4.shared.b16 {%0,%1,%2,%3}, [%4];"
        : "=r"(r[0]), "=r"(r[1]), "=r"(r[2]), "=r"(r[3]) : "r"(addr));
}
__device__ __forceinline__ void ldm_x4_t(uint32_t* r, uint32_t addr) {
    asm volatile("ldmatrix.sync.aligned.m8n8.x4.trans.shared.b16 {%0,%1,%2,%3}, [%4];"
        : "=r"(r[0]), "=r"(r[1]), "=r"(r[2]), "=r"(r[3]) : "r"(addr));
}
__device__ __forceinline__ float fast_exp2(float y) {
    y = fmaxf(y, -125.0f);
    int j = __float2int_rn(y);
    float f = y - (float)j;
    float p = 1.535336188319500e-4f;
    p = fmaf(p, f, 1.339887440266574e-3f);
    p = fmaf(p, f, 9.618437357674640e-3f);
    p = fmaf(p, f, 5.550332471162809e-2f);
    p = fmaf(p, f, 2.402264791363012e-1f);
    p = fmaf(p, f, 6.931472028550421e-1f);
    p = fmaf(p, f, 1.0f);
    return p * __int_as_float((j + 127) << 23);
}

// ---------------------------------------------------------------------------
// Split-bf16 GEMM: C[M,N] = A[M,K] * W[N,K]^T.  CTA 128x128, BK=32.
// gmem fp32 -> regs -> bf16 hi/lo smem planes (64B pitch, XOR-swizzled);
// fragments via ldmatrix; 3-term bf16 k16 MMAs. 8 warps (4x2), warp 32x64.
// ---------------------------------------------------------------------------
__global__ __launch_bounds__(256) void gemm_tc(
    const float* __restrict__ A, const float* __restrict__ W,
    float* __restrict__ C, int permute)
{
    __shared__ __align__(16) unsigned char smraw[32768];
    const uint32_t smb = (uint32_t)__cvta_generic_to_shared(smraw);
    const uint32_t AHI = smb, ALO = smb + 8192, WHI = smb + 16384, WLO = smb + 24576;

    const int tid  = threadIdx.x;
    const int lane = tid & 31, widx = tid >> 5;
    const int ty = lane >> 2, tq = lane & 3;
    const int wm = widx & 3, wn = widx >> 2;
    const int m0 = blockIdx.y * 128, n0 = blockIdx.x * 128;
    const int ldrow = tid >> 3, ldc = tid & 7;
    const int lrow = lane & 15, kh = lane >> 4;

    float acc[2][8][4];
#pragma unroll
    for (int mf = 0; mf < 2; mf++)
#pragma unroll
        for (int f = 0; f < 8; f++)
#pragma unroll
            for (int e = 0; e < 4; e++) acc[mf][f][e] = 0.f;

    float4 stA[4], stW[4];

    auto ldg = [&](int t) {
        const float* Ab = A + (size_t)(m0 + ldrow) * DIM_ + t * 32 + ldc * 4;
        const float* Wb = W + (size_t)(n0 + ldrow) * DIM_ + t * 32 + ldc * 4;
#pragma unroll
        for (int i = 0; i < 4; i++) {
            stA[i] = *(const float4*)(Ab + (size_t)i * 32 * DIM_);
            stW[i] = *(const float4*)(Wb + (size_t)i * 32 * DIM_);
        }
    };
    auto sts = [&]() {
#pragma unroll
        for (int i = 0; i < 4; i++) {
            const int row = ldrow + i * 32;
            const uint32_t off = (uint32_t)row * 64u +
                (uint32_t)(((ldc >> 1) ^ ((row >> 1) & 3)) * 16) + (uint32_t)((ldc & 1) * 8);
            uint32_t h0, l0, h1, l1;
            bf16_split2(stA[i].x, stA[i].y, h0, l0);
            bf16_split2(stA[i].z, stA[i].w, h1, l1);
            asm volatile("st.shared.v2.b32 [%0], {%1,%2};" :: "r"(AHI + off), "r"(h0), "r"(h1));
            asm volatile("st.shared.v2.b32 [%0], {%1,%2};" :: "r"(ALO + off), "r"(l0), "r"(l1));
            bf16_split2(stW[i].x, stW[i].y, h0, l0);
            bf16_split2(stW[i].z, stW[i].w, h1, l1);
            asm volatile("st.shared.v2.b32 [%0], {%1,%2};" :: "r"(WHI + off), "r"(h0), "r"(h1));
            asm volatile("st.shared.v2.b32 [%0], {%1,%2};" :: "r"(WLO + off), "r"(l0), "r"(l1));
        }
    };

    ldg(0);
    for (int t = 0; t < DIM_ / 32; t++) {
        __syncthreads();
        sts();
        __syncthreads();
        if (t + 1 < DIM_ / 32) ldg(t + 1);

#pragma unroll
        for (int ks = 0; ks < 2; ks++) {
            uint32_t Ah[2][4], Al[2][4];
#pragma unroll
            for (int mf = 0; mf < 2; mf++) {
                const int row = wm * 32 + mf * 16 + lrow;
                const int seg = ks * 2 + kh;
                const uint32_t off = (uint32_t)row * 64u +
                    (uint32_t)((seg ^ ((row >> 1) & 3)) * 16);
                ldm_x4(Ah[mf], AHI + off);
                ldm_x4(Al[mf], ALO + off);
            }
#pragma unroll
            for (int nb = 0; nb < 4; nb++) {
                const int row = wn * 64 + nb * 16 + lrow;
                const int seg = ks * 2 + kh;
                const uint32_t off = (uint32_t)row * 64u +
                    (uint32_t)((seg ^ ((row >> 1) & 3)) * 16);
                uint32_t Bh[4], Bl[4];
                ldm_x4(Bh, WHI + off);
                ldm_x4(Bl, WLO + off);
#pragma unroll
                for (int g = 0; g < 2; g++) {
                    uint32_t bh2[2] = {Bh[g], Bh[2 + g]};
                    uint32_t bl2[2] = {Bl[g], Bl[2 + g]};
                    const int f = nb * 2 + g;
#pragma unroll
                    for (int mf = 0; mf < 2; mf++) {
                        mma_bf16(acc[mf][f], Ah[mf], bh2);
                        mma_bf16(acc[mf][f], Ah[mf], bl2);
                        mma_bf16(acc[mf][f], Al[mf], bh2);
                    }
                }
            }
        }
    }

    if (!permute) {
#pragma unroll
        for (int mf = 0; mf < 2; mf++) {
            const int rg = m0 + wm * 32 + mf * 16 + ty;
#pragma unroll
            for (int f = 0; f < 8; f++) {
                const int cg = n0 + wn * 64 + f * 8 + 2 * tq;
                *(float2*)&C[(size_t)rg * DIM_ + cg] =
                    make_float2(acc[mf][f][0], acc[mf][f][1]);
                *(float2*)&C[(size_t)(rg + 8) * DIM_ + cg] =
                    make_float2(acc[mf][f][2], acc[mf][f][3]);
            }
        }
    } else {
#pragma unroll
        for (int mf = 0; mf < 2; mf++) {
            const int rbase = m0 + wm * 32 + mf * 16 + ty;
#pragma unroll
            for (int f = 0; f < 8; f++) {
#pragma unroll
                for (int e = 0; e < 4; e++) {
                    const int rg = rbase + (e >> 1) * 8;
                    const int bb = rg >> 11, ql2 = rg & (L_ - 1);
                    const int cg = n0 + wn * 64 + f * 8 + 2 * tq + (e & 1);
                    const int hh = cg & 15, dk = cg >> 4;
                    C[(((size_t)bb * H_ + hh) * L_ + ql2) * DK_ + dk] = acc[mf][f][e];
                }
            }
        }
    }
}

// ---------------------------------------------------------------------------
// Split-bf16 mma.sync flash attention.
// 128 q/CTA (8 warps x 16 rows), 64 keys/iter, dk=64. K/V: gmem fp32 -> regs
// -> bf16 hi/lo planes (128B pitch, SW128). Q frags in regs. P packed bf16
// hi/lo from softmax regs. V B-frags via ldmatrix.trans. Mask: cp.async x2.
// ---------------------------------------------------------------------------
#define APW 68
#define MASK_ST (128 * APW)
#define AT_KHI 0
#define AT_KLO 8192
#define AT_VHI 16384
#define AT_VLO 24576
#define AT_PHI 32768
#define AT_PLO 49152
#define AT_MSK 65536
#define ATTN_SMEM (AT_MSK + 2 * MASK_ST * 4)   // 135168 bytes

__global__ __launch_bounds__(256) void attn_tc(
    const float* __restrict__ Q, const float* __restrict__ K,
    const float* __restrict__ V, const void* __restrict__ maskp,
    float* __restrict__ mha)
{
    extern __shared__ unsigned char sab[];
    const uint32_t smb = (uint32_t)__cvta_generic_to_shared(sab);

    const int tid  = threadIdx.x;
    const int lane = tid & 31, w = tid >> 5;
    const int ty = lane >> 2, tq = lane & 3;
    const int lrow = lane & 15, kh = lane >> 4;
    const int bh = blockIdx.y;
    const int b  = bh >> 4, h = bh & 15;
    const int q0 = blockIdx.x * 128;
    const int mode = g_mask_mode;

    const float* Qh = Q + (size_t)bh * L_ * DK_;
    const float* Kh = K + (size_t)bh * L_ * DK_;
    const float* Vh = V + (size_t)bh * L_ * DK_;

    // Q fragments (loop-invariant) split to bf16 hi/lo
    uint32_t qfh[4][4], qfl[4][4];
    {
        const float* qp0 = Qh + (size_t)(q0 + w * 16 + ty) * DK_;
        const float* qp1 = qp0 + 8 * DK_;
#pragma unroll
        for (int ks = 0; ks < 4; ks++) {
            float2 x0 = *(const float2*)(qp0 + ks * 16 + 2 * tq);
            float2 x1 = *(const float2*)(qp1 + ks * 16 + 2 * tq);
            float2 x2 = *(const float2*)(qp0 + ks * 16 + 2 * tq + 8);
            float2 x3 = *(const float2*)(qp1 + ks * 16 + 2 * tq + 8);
            bf16_split2(x0.x, x0.y, qfh[ks][0], qfl[ks][0]);
            bf16_split2(x1.x, x1.y, qfh[ks][1], qfl[ks][1]);
            bf16_split2(x2.x, x2.y, qfh[ks][2], qfl[ks][2]);
            bf16_split2(x3.x, x3.y, qfh[ks][3], qfl[ks][3]);
        }
    }

    float m_[2] = {-INFINITY, -INFINITY}, l_[2] = {0.f, 0.f};
    float acc[8][4];
#pragma unroll
    for (int f = 0; f < 8; f++)
#pragma unroll
        for (int e = 0; e < 4; e++) acc[f][e] = 0.f;

    float4 stK[4], stV[4];
    const int krow = tid >> 4, kc = tid & 15;

    auto ldg_kv = [&](int t) {
        const float* Kg = Kh + (size_t)t * 64 * DK_ + (size_t)krow * DK_ + kc * 4;
        const float* Vg = Vh + (size_t)t * 64 * DK_ + (size_t)krow * DK_ + kc * 4;
#pragma unroll
        for (int i = 0; i < 4; i++) {
            stK[i] = *(const float4*)(Kg + (size_t)i * 16 * DK_);
            stV[i] = *(const float4*)(Vg + (size_t)i * 16 * DK_);
        }
    };
    auto sts_kv = [&]() {
#pragma unroll
        for (int i = 0; i < 4; i++) {
            const int row = krow + i * 16;
            const uint32_t off = (uint32_t)row * 128u +
                (uint32_t)((((kc >> 1) ^ (row & 7)) * 16)) + (uint32_t)((kc & 1) * 8);
            uint32_t h0, l0, h1, l1;
            bf16_split2(stK[i].x, stK[i].y, h0, l0);
            bf16_split2(stK[i].z, stK[i].w, h1, l1);
            asm volatile("st.shared.v2.b32 [%0], {%1,%2};" :: "r"(smb + AT_KHI + off), "r"(h0), "r"(h1));
            asm volatile("st.shared.v2.b32 [%0], {%1,%2};" :: "r"(smb + AT_KLO + off), "r"(l0), "r"(l1));
            bf16_split2(stV[i].x, stV[i].y, h0, l0);
            bf16_split2(stV[i].z, stV[i].w, h1, l1);
            asm volatile("st.shared.v2.b32 [%0], {%1,%2};" :: "r"(smb + AT_VHI + off), "r"(h0), "r"(h1));
            asm volatile("st.shared.v2.b32 [%0], {%1,%2};" :: "r"(smb + AT_VLO + off), "r"(l0), "r"(l1));
        }
    };

#define PREFETCH_MASK(t_, s_) do {                                              \
        float* Md_ = (float*)(sab + AT_MSK) + (s_) * MASK_ST;                   \
        if (mode != 1) {                                                        \
            const uint32_t* Mg_ = (const uint32_t*)maskp +                      \
                ((size_t)b * L_ + q0) * L_ + (size_t)(t_) * 64;                 \
            _Pragma("unroll")                                                   \
            for (int i_ = 0; i_ < 8; i_++) {                                    \
                int idx_ = tid + i_ * 256;                                      \
                int r_ = idx_ >> 4, c4_ = (idx_ & 15) * 4;                      \
                asm volatile("cp.async.cg.shared.global [%0], [%1], 16;"        \
                    :: "r"((uint32_t)__cvta_generic_to_shared(Md_ + r_ * APW + c4_)),\
                       "l"(Mg_ + (size_t)r_ * L_ + c4_) : "memory");            \
            }                                                                   \
        } else {                                                                \
            const unsigned char* Mg_ = (const unsigned char*)maskp +            \
                ((size_t)b * L_ + q0) * L_ + (size_t)(t_) * 64;                 \
            _Pragma("unroll")                                                   \
            for (int i_ = 0; i_ < 2; i_++) {                                    \
                int idx_ = tid + i_ * 256;                                      \
                int r_ = idx_ >> 2, c16_ = (idx_ & 3) * 16;                     \
                asm volatile("cp.async.cg.shared.global [%0], [%1], 16;"        \
                    :: "r"((uint32_t)__cvta_generic_to_shared((char*)Md_ + r_ * (APW * 4) + c16_)),\
                       "l"(Mg_ + (size_t)r_ * L_ + c16_) : "memory");           \
            }                                                                   \
        }                                                                       \
        asm volatile("cp.async.commit_group;" ::: "memory");                    \
    } while (0)

    PREFETCH_MASK(0, 0);
    ldg_kv(0);

    const int rA = w * 16 + ty, rB = rA + 8;

    for (int t = 0; t < L_ / 64; t++) {
        __syncthreads();                       // prior compute done; smem free
        sts_kv();
        if (t + 1 < L_ / 64) {
            PREFETCH_MASK(t + 1, (t + 1) & 1);
            ldg_kv(t + 1);
            asm volatile("cp.async.wait_group 1;" ::: "memory");
        } else {
            asm volatile("cp.async.wait_group 0;" ::: "memory");
        }
        __syncthreads();                       // K/V + mask(t) visible

        const uint32_t* Mw = (const uint32_t*)(sab + AT_MSK) + (t & 1) * MASK_ST;
        const unsigned char* Mb = (const unsigned char*)Mw;

        // S = Q K^T
        float s[8][4];
#pragma unroll
        for (int f = 0; f < 8; f++)
#pragma unroll
            for (int e = 0; e < 4; e++) s[f][e] = 0.f;

#pragma unroll
        for (int ks = 0; ks < 4; ks++) {
#pragma unroll
            for (int kb = 0; kb < 4; kb++) {
                const int krw = kb * 16 + lrow;
                const uint32_t koff = (uint32_t)krw * 128u +
                    (uint32_t)((((ks * 2 + kh) ^ (krw & 7)) * 16));
                uint32_t Bh4[4], Bl4[4];
                ldm_x4(Bh4, smb + AT_KHI + koff);
                ldm_x4(Bl4, smb + AT_KLO + koff);
#pragma unroll
                for (int g = 0; g < 2; g++) {
                    uint32_t bh2[2] = {Bh4[g], Bh4[2 + g]};
                    uint32_t bl2[2] = {Bl4[g], Bl4[2 + g]};
                    const int f = kb * 2 + g;
                    mma_bf16(s[f], qfh[ks], bh2);
                    mma_bf16(s[f], qfh[ks], bl2);
                    mma_bf16(s[f], qfl[ks], bh2);
                }
            }
        }

        // scale + additive mask
#pragma unroll
        for (int nf = 0; nf < 8; nf++) {
            const int c0 = nf * 8 + 2 * tq;
#pragma unroll
            for (int e = 0; e < 2; e++) {
                bool mA, mB;
                if (mode == 1) {
                    mA = Mb[rA * (APW * 4) + c0 + e] != 0;
                    mB = Mb[rB * (APW * 4) + c0 + e] != 0;
                } else {
                    mA = Mw[rA * APW + c0 + e] != 0u;
                    mB = Mw[rB * APW + c0 + e] != 0u;
                }
                s[nf][e]     = s[nf][e]     * 0.125f + (mA ? NEGV : 0.f);
                s[nf][e + 2] = s[nf][e + 2] * 0.125f + (mB ? NEGV : 0.f);
            }
        }

        // online softmax + P pack to bf16 hi/lo planes
        float mxA = -INFINITY, mxB = -INFINITY;
#pragma unroll
        for (int nf = 0; nf < 8; nf++) {
            mxA = fmaxf(mxA, fmaxf(s[nf][0], s[nf][1]));
            mxB = fmaxf(mxB, fmaxf(s[nf][2], s[nf][3]));
        }
        mxA = fmaxf(mxA, __shfl_xor_sync(0xffffffffu, mxA, 1));
        mxA = fmaxf(mxA, __shfl_xor_sync(0xffffffffu, mxA, 2));
        mxB = fmaxf(mxB, __shfl_xor_sync(0xffffffffu, mxB, 1));
        mxB = fmaxf(mxB, __shfl_xor_sync(0xffffffffu, mxB, 2));

        const float mnA = fmaxf(m_[0], mxA), mnB = fmaxf(m_[1], mxB);
        const float corrA = fast_exp2((m_[0] - mnA) * LOG2E);
        const float corrB = fast_exp2((m_[1] - mnB) * LOG2E);
        m_[0] = mnA; m_[1] = mnB;

        float sumA = 0.f, sumB = 0.f;
#pragma unroll
        for (int nf = 0; nf < 8; nf++) {
            float p0 = fast_exp2((s[nf][0] - mnA) * LOG2E);
            float p1 = fast_exp2((s[nf][1] - mnA) * LOG2E);
            float p2 = fast_exp2((s[nf][2] - mnB) * LOG2E);
            float p3 = fast_exp2((s[nf][3] - mnB) * LOG2E);
            sumA += p0 + p1; sumB += p2 + p3;
            uint32_t ph, pl;
            bf16_split2(p0, p1, ph, pl);
            const uint32_t offA = (uint32_t)rA * 128u +
                (uint32_t)(((nf ^ (rA & 7)) * 16)) + (uint32_t)(tq * 4);
            asm volatile("st.shared.b32 [%0], %1;" :: "r"(smb + AT_PHI + offA), "r"(ph));
            asm volatile("st.shared.b32 [%0], %1;" :: "r"(smb + AT_PLO + offA), "r"(pl));
            bf16_split2(p2, p3, ph, pl);
            const uint32_t offB = (uint32_t)rB * 128u +
                (uint32_t)(((nf ^ (rB & 7)) * 16)) + (uint32_t)(tq * 4);
            asm volatile("st.shared.b32 [%0], %1;" :: "r"(smb + AT_PHI + offB), "r"(ph));
            asm volatile("st.shared.b32 [%0], %1;" :: "r"(smb + AT_PLO + offB), "r"(pl));
        }
        sumA += __shfl_xor_sync(0xffffffffu, sumA, 1);
        sumA += __shfl_xor_sync(0xffffffffu, sumA, 2);
        sumB += __shfl_xor_sync(0xffffffffu, sumB, 1);
        sumB += __shfl_xor_sync(0xffffffffu, sumB, 2);
        l_[0] = l_[0] * corrA + sumA;
        l_[1] = l_[1] * corrB + sumB;
#pragma unroll
        for (int f = 0; f < 8; f++) {
            acc[f][0] *= corrA; acc[f][1] *= corrA;
            acc[f][2] *= corrB; acc[f][3] *= corrB;
        }
        __syncwarp();

        // O += P V
#pragma unroll
        for (int ks = 0; ks < 4; ks++) {
            const int prow = w * 16 + lrow;
            const uint32_t poff = (uint32_t)prow * 128u +
                (uint32_t)((((ks * 2 + kh) ^ (prow & 7)) * 16));
            uint32_t Ph4[4], Pl4[4];
            ldm_x4(Ph4, smb + AT_PHI + poff);
            ldm_x4(Pl4, smb + AT_PLO + poff);
#pragma unroll
            for (int db = 0; db < 4; db++) {
                const int vrow = ks * 16 + (lane & 7) + ((lane >> 4) & 1) * 8;
                const int vseg = db * 2 + ((lane >> 3) & 1);
                const uint32_t voff = (uint32_t)vrow * 128u +
                    (uint32_t)(((vseg ^ (vrow & 7)) * 16));
                uint32_t Vh4[4], Vl4[4];
                ldm_x4_t(Vh4, smb + AT_VHI + voff);
                ldm_x4_t(Vl4, smb + AT_VLO + voff);
#pragma unroll
                for (int g = 0; g < 2; g++) {
                    uint32_t vh2[2] = {Vh4[g], Vh4[2 + g]};
                    uint32_t vl2[2] = {Vl4[g], Vl4[2 + g]};
                    const int f = db * 2 + g;
                    mma_bf16(acc[f], Ph4, vh2);
                    mma_bf16(acc[f], Ph4, vl2);
                    mma_bf16(acc[f], Pl4, vh2);
                }
            }
        }
    }
#undef PREFETCH_MASK

    // normalize + interleaved store (channel = dk*16 + h)
    const float invA = 1.f / l_[0], invB = 1.f / l_[1];
    const int qA = q0 + rA, qB = q0 + rB;
    float* dA = mha + ((size_t)b * L_ + qA) * DIM_ + h;
    float* dB = mha + ((size_t)b * L_ + qB) * DIM_ + h;
#pragma unroll
    for (int nf = 0; nf < 8; nf++) {
        const int c0 = nf * 8 + 2 * tq;
        dA[c0 * 16]       = acc[nf][0] * invA;
        dA[(c0 + 1) * 16] = acc[nf][1] * invA;
        dB[c0 * 16]       = acc[nf][2] * invB;
        dB[(c0 + 1) * 16] = acc[nf][3] * invB;
    }
}

// ---------------------------------------------------------------------------
extern "C" void kernel_launch(void* const* d_in, const int* in_sizes, int n_in,
                              void* d_out, int out_size)
{
    const float* q   = (const float*)d_in[0];
    const float* k   = (const float*)d_in[1];
    const float* v   = (const float*)d_in[2];
    const void*  msk = d_in[3];
    const float* Wq  = (const float*)d_in[4];
    const float* Wk  = (const float*)d_in[5];
    const float* Wv  = (const float*)d_in[6];
    const float* Wo  = (const float*)d_in[7];
    float* out = (float*)d_out;

    float *gq, *gk, *gv, *gm;
    cudaGetSymbolAddress((void**)&gq, g_Q);
    cudaGetSymbolAddress((void**)&gk, g_K);
    cudaGetSymbolAddress((void**)&gv, g_V);
    cudaGetSymbolAddress((void**)&gm, g_MHA);

    cudaFuncSetAttribute(attn_tc, cudaFuncAttributeMaxDynamicSharedMemorySize,
                         ATTN_SMEM);

    detect_mask_kernel<<<1, 256>>>((const unsigned int*)msk);

    dim3 ggrid(DIM_ / 128, M_ / 128);   // (8, 32)
    gemm_tc<<<ggrid, 256>>>(q, Wq, gq, 1);
    gemm_tc<<<ggrid, 256>>>(k, Wk, gk, 1);
    gemm_tc<<<ggrid, 256>>>(v, Wv, gv, 1);

    attn_tc<<<dim3(L_ / 128, B_ * H_), 256, ATTN_SMEM>>>(gq, gk, gv, msk, gm);

    gemm_tc<<<ggrid, 256>>>(gm, Wo, out, 0);
}